// round 8
// baseline (speedup 1.0000x reference)
#include <cuda_runtime.h>
#include <cuda_bf16.h>
#include <cstdint>

#define BB 16
#define CC 64
#define NN 2048
#define TQ 64      // queries per CTA (half of a 128x128 triangle tile)
#define TM 128     // candidates per CTA
#define RS 144     // bf16 tile row stride (bytes)
#define SROW 129   // fp32 score row stride (words)
#define NSLOT 48   // partial-list slots per query: row J at slot J, col (I,h) at 16+2I+h

// smem byte offsets; S (64x129 fp32 = 33024 B) aliases A/B region after MMA.
#define AHI 0
#define ALO 9216
#define BHI 18432
#define BLO 36864
#define XXA 55296          // 64 fp32 (I-half candidate norms)
#define XXB 55552          // 128 fp32 (J-block candidate norms)
#define SM_TOTAL 56320

// ---------------- scratch (no allocation allowed) ----------------
__device__ __nv_bfloat16 g_hi[BB * NN * CC];
__device__ __nv_bfloat16 g_lo[BB * NN * CC];
__device__ float         g_xx[BB * NN];
__device__ float         g_pv[(size_t)BB * NN * NSLOT * 9];
__device__ int           g_pi[(size_t)BB * NN * NSLOT * 9];
__device__ int           g_idx[BB * NN * 8];

__device__ __forceinline__ uint32_t smem_u32(const void* p) {
    uint32_t a;
    asm("{ .reg .u64 t; cvta.to.shared.u64 t, %1; cvt.u32.u64 %0, t; }" : "=r"(a) : "l"(p));
    return a;
}
__device__ __forceinline__ void ldsm4(uint32_t& r0, uint32_t& r1, uint32_t& r2, uint32_t& r3,
                                      uint32_t addr) {
    asm volatile("ldmatrix.sync.aligned.m8n8.x4.shared.b16 {%0,%1,%2,%3}, [%4];"
                 : "=r"(r0), "=r"(r1), "=r"(r2), "=r"(r3) : "r"(addr));
}
__device__ __forceinline__ void mma16816(float* c, const uint32_t* a, uint32_t b0, uint32_t b1) {
    asm volatile(
        "mma.sync.aligned.m16n8k16.row.col.f32.bf16.bf16.f32 "
        "{%0,%1,%2,%3}, {%4,%5,%6,%7}, {%8,%9}, {%0,%1,%2,%3};"
        : "+f"(c[0]), "+f"(c[1]), "+f"(c[2]), "+f"(c[3])
        : "r"(a[0]), "r"(a[1]), "r"(a[2]), "r"(a[3]), "r"(b0), "r"(b1));
}

// lexicographic top-9 insert: (val desc, idx asc) == top_k semantics, order-free
#define INS9(v, ii)                                                            \
    if ((v) > val9[8] || ((v) == val9[8] && (ii) < idx9[8])) {                 \
        val9[8] = (v); idx9[8] = (ii);                                         \
        _Pragma("unroll")                                                      \
        for (int k = 8; k > 0; --k) {                                          \
            if (val9[k] > val9[k - 1] ||                                       \
                (val9[k] == val9[k - 1] && idx9[k] < idx9[k - 1])) {           \
                float tv = val9[k]; val9[k] = val9[k - 1]; val9[k - 1] = tv;   \
                int ti_ = idx9[k]; idx9[k] = idx9[k - 1]; idx9[k - 1] = ti_;   \
            }                                                                  \
        }                                                                      \
    }

// ---------------------------------------------------------------------------
// Prep: hi/lo bf16 split, transposed [b][n][c] + fp32 norms.
// ---------------------------------------------------------------------------
__global__ void prep_kernel(const float* __restrict__ x) {
    int b = blockIdx.y;
    int n = blockIdx.x * 128 + threadIdx.x;
    const float* xp = x + b * CC * NN + n;
    __nv_bfloat162 hi2[32], lo2[32];
    float s = 0.f;
#pragma unroll
    for (int c2 = 0; c2 < 32; ++c2) {
        float v0 = xp[(2 * c2) * NN];
        float v1 = xp[(2 * c2 + 1) * NN];
        s = fmaf(v0, v0, s);
        s = fmaf(v1, v1, s);
        __nv_bfloat16 h0 = __float2bfloat16(v0);
        __nv_bfloat16 h1 = __float2bfloat16(v1);
        float r0 = v0 - __bfloat162float(h0);
        float r1 = v1 - __bfloat162float(h1);
        hi2[c2] = __halves2bfloat162(h0, h1);
        lo2[c2] = __halves2bfloat162(__float2bfloat16(r0), __float2bfloat16(r1));
    }
    g_xx[b * NN + n] = s;
    size_t rowo = (size_t)(b * NN + n) * CC;
    uint4* dh = (uint4*)(g_hi + rowo);
    uint4* dl = (uint4*)(g_lo + rowo);
    const uint4* sh = (const uint4*)hi2;
    const uint4* sl = (const uint4*)lo2;
#pragma unroll
    for (int i = 0; i < 8; ++i) { dh[i] = sh[i]; dl[i] = sl[i]; }
}

// ---------------------------------------------------------------------------
// KNN: one CTA = one 64x128 half of an upper-triangle tile (ti <= tj).
// R4's exact MMA body (32 acc regs/thread — saturating) + symmetric reuse:
// row scan for the 64 I-half queries, col scan for the 128 J-block queries.
// ---------------------------------------------------------------------------
__global__ void __launch_bounds__(256, 2) knn_kernel() {
    extern __shared__ char sm[];
    const uint32_t sb = smem_u32(sm);
    const int tid  = threadIdx.x;
    const int lane = tid & 31;
    const int w    = tid >> 5;
    const int wm   = (w & 1) * 32;        // warp query-row offset (0/32)
    const int wn   = (w >> 1) * 32;       // warp candidate-col offset (0..96)
    const int b    = blockIdx.y;

    // decode: pair p -> triangle tile (ti, tj); h = which 64-row half of ti's block
    int p = blockIdx.x >> 1;
    const int h = blockIdx.x & 1;
    int ti = 0;
    while (p >= 16 - ti) { p -= 16 - ti; ++ti; }
    const int tj = ti + p;

    float* S   = (float*)sm;              // aliases A/B after MMA
    float* xxA = (float*)(sm + XXA);
    float* xxB = (float*)(sm + XXB);

    // ---- load tiles ----
    {
        const uint4* ah = (const uint4*)(g_hi + (size_t)(b * NN + ti * 128 + h * 64) * CC);
        const uint4* al = (const uint4*)(g_lo + (size_t)(b * NN + ti * 128 + h * 64) * CC);
        for (int i = tid; i < 512; i += 256) {
            int row = i >> 3, seg = i & 7;
            int o = row * RS + seg * 16;
            *(uint4*)(sm + AHI + o) = ah[i];
            *(uint4*)(sm + ALO + o) = al[i];
        }
        const uint4* bh = (const uint4*)(g_hi + (size_t)(b * NN + tj * 128) * CC);
        const uint4* bl = (const uint4*)(g_lo + (size_t)(b * NN + tj * 128) * CC);
        for (int i = tid; i < 1024; i += 256) {
            int row = i >> 3, seg = i & 7;
            int o = row * RS + seg * 16;
            *(uint4*)(sm + BHI + o) = bh[i];
            *(uint4*)(sm + BLO + o) = bl[i];
        }
        if (tid < 64)                      xxA[tid] = g_xx[b * NN + ti * 128 + h * 64 + tid];
        else if (tid < 192)                xxB[tid - 64] = g_xx[b * NN + tj * 128 + (tid - 64)];
    }
    __syncthreads();

    // ---- MMA: 64x128 half-tile, 3-pass bf16 split (R4 body verbatim) ----
    float acc[2][4][4];
#pragma unroll
    for (int i = 0; i < 2; ++i)
#pragma unroll
        for (int j = 0; j < 4; ++j)
#pragma unroll
            for (int k = 0; k < 4; ++k) acc[i][j][k] = 0.f;

    const int lrow = lane & 15;
    const int lcol = (lane >> 4) * 16;
    const uint32_t aHiB = sb + AHI + (wm + lrow) * RS + lcol;
    const uint32_t aLoB = sb + ALO + (wm + lrow) * RS + lcol;
    const uint32_t bHiB = sb + BHI + (wn + lrow) * RS + lcol;
    const uint32_t bLoB = sb + BLO + (wn + lrow) * RS + lcol;

#pragma unroll
    for (int ks = 0; ks < 4; ++ks) {
        const int ko = ks * 32;
        uint32_t aH[2][4], aL[2][4], bH[4][2], bL[4][2];
#pragma unroll
        for (int m2 = 0; m2 < 2; ++m2) {
            ldsm4(aH[m2][0], aH[m2][1], aH[m2][2], aH[m2][3], aHiB + m2 * 16 * RS + ko);
            ldsm4(aL[m2][0], aL[m2][1], aL[m2][2], aL[m2][3], aLoB + m2 * 16 * RS + ko);
        }
#pragma unroll
        for (int np = 0; np < 2; ++np) {
            uint32_t r0, r1, r2, r3;
            ldsm4(r0, r1, r2, r3, bHiB + np * 16 * RS + ko);
            bH[np * 2][0] = r0; bH[np * 2][1] = r2;
            bH[np * 2 + 1][0] = r1; bH[np * 2 + 1][1] = r3;
            ldsm4(r0, r1, r2, r3, bLoB + np * 16 * RS + ko);
            bL[np * 2][0] = r0; bL[np * 2][1] = r2;
            bL[np * 2 + 1][0] = r1; bL[np * 2 + 1][1] = r3;
        }
#pragma unroll
        for (int m2 = 0; m2 < 2; ++m2)
#pragma unroll
            for (int j = 0; j < 4; ++j) {
                mma16816(acc[m2][j], aH[m2], bH[j][0], bH[j][1]);
                mma16816(acc[m2][j], aH[m2], bL[j][0], bL[j][1]);
                mma16816(acc[m2][j], aL[m2], bH[j][0], bH[j][1]);
            }
    }
    __syncthreads();   // tiles consumed; S may overwrite

    // ---- spill S[q][m], q in 0..63, m in 0..127 ----
    {
        const int r  = lane >> 2;
        const int cp = (lane & 3) * 2;
#pragma unroll
        for (int m2 = 0; m2 < 2; ++m2)
#pragma unroll
            for (int j = 0; j < 4; ++j) {
                int row = wm + m2 * 16 + r;
                int col = wn + j * 8 + cp;
                S[row * SROW + col]           = acc[m2][j][0];
                S[row * SROW + col + 1]       = acc[m2][j][1];
                S[(row + 8) * SROW + col]     = acc[m2][j][2];
                S[(row + 8) * SROW + col + 1] = acc[m2][j][3];
            }
    }
    __syncthreads();

    // ---- scans ----
    float val9[9];
    int   idx9[9];
#pragma unroll
    for (int k = 0; k < 9; ++k) { val9[k] = -3.4e38f; idx9[k] = 0x7FFFFFFF; }

    if (tid < 64) {
        // row scan: query = ti*128 + h*64 + tid, cands = block tj (128)
        const float* srow = &S[tid * SROW];
        const int base = tj * 128;
        for (int m = 0; m < 128; ++m) {
            float v = fmaf(2.f, srow[m], -xxB[m]);
            INS9(v, base + m);
        }
        size_t o = ((size_t)(b * NN + ti * 128 + h * 64 + tid) * NSLOT + tj) * 9;
#pragma unroll
        for (int k = 0; k < 9; ++k) { g_pv[o + k] = val9[k]; g_pi[o + k] = idx9[k]; }
    } else if (tid < 192 && ti != tj) {
        // col scan: query = tj*128 + (tid-64), cands = I-half (64)
        const int jq = tid - 64;
        const int base = ti * 128 + h * 64;
        for (int m = 0; m < 64; ++m) {
            float v = fmaf(2.f, S[m * SROW + jq], -xxA[m]);
            INS9(v, base + m);
        }
        size_t o = ((size_t)(b * NN + tj * 128 + jq) * NSLOT + 16 + 2 * ti + h) * 9;
#pragma unroll
        for (int k = 0; k < 9; ++k) { g_pv[o + k] = val9[k]; g_pi[o + k] = idx9[k]; }
    }
}

// ---------------------------------------------------------------------------
// Merge: query block t reads row slots J=t..15 and col slots 16+2I+h, I<t.
// Lists sorted (val desc, idx asc); lexicographic insert is order-free.
// ---------------------------------------------------------------------------
__global__ void merge_kernel() {
    int q = blockIdx.x * 256 + threadIdx.x;
    const int t = (q >> 7) & 15;
    const float* pv = g_pv + (size_t)q * NSLOT * 9;
    const int*   pi = g_pi + (size_t)q * NSLOT * 9;
    float val9[9];
    int   idx9[9];
#pragma unroll
    for (int k = 0; k < 9; ++k) { val9[k] = -3.4e38f; idx9[k] = 0x7FFFFFFF; }

    auto consume = [&](int s) {
#pragma unroll
        for (int k = 0; k < 9; ++k) {
            float v = pv[s * 9 + k];
            int  ii = pi[s * 9 + k];
            if (!(v > val9[8] || (v == val9[8] && ii < idx9[8]))) break;
            INS9(v, ii);
        }
    };
    for (int J = t; J < 16; ++J) consume(J);
    for (int I = 0; I < t; ++I) { consume(16 + 2 * I); consume(16 + 2 * I + 1); }

    int* gout = &g_idx[(size_t)q * 8];
#pragma unroll
    for (int k = 0; k < 8; ++k) gout[k] = idx9[k + 1];   // rank 0 = self
}

// ---------------------------------------------------------------------------
// Output assembly:
// out[b,c,n] = x[b,c,n];  out[b,c,N+n] = mean_k x[b,c,idx[b,n,k]]
// ---------------------------------------------------------------------------
__global__ void gather_kernel(const float* __restrict__ x, float* __restrict__ out) {
    __shared__ float row[NN];
    int b = blockIdx.x >> 6;
    int c = blockIdx.x & 63;
    const float* xr = x + (b * CC + c) * NN;
    for (int n = threadIdx.x; n < NN; n += blockDim.x) row[n] = xr[n];
    __syncthreads();
    const int4* gi = (const int4*)(g_idx + (size_t)b * NN * 8);
    float* o = out + (size_t)(b * CC + c) * (2 * NN);
    for (int n = threadIdx.x; n < NN; n += blockDim.x) {
        o[n] = row[n];
        int4 i0 = gi[n * 2];
        int4 i1 = gi[n * 2 + 1];
        float s = row[i0.x] + row[i0.y] + row[i0.z] + row[i0.w]
                + row[i1.x] + row[i1.y] + row[i1.z] + row[i1.w];
        o[NN + n] = s * 0.125f;
    }
}

// ---------------------------------------------------------------------------
extern "C" void kernel_launch(void* const* d_in, const int* in_sizes, int n_in,
                              void* d_out, int out_size) {
    (void)in_sizes; (void)n_in; (void)out_size;
    const float* x = (const float*)d_in[0];
    float* out = (float*)d_out;

    prep_kernel<<<dim3(16, 16), 128>>>(x);

    cudaFuncSetAttribute(knn_kernel, cudaFuncAttributeMaxDynamicSharedMemorySize, SM_TOTAL);
    knn_kernel<<<dim3(272, 16), 256, SM_TOTAL>>>();

    merge_kernel<<<(BB * NN) / 256, 256>>>();

    gather_kernel<<<BB * CC, 256>>>(x, out);
}

// round 9
// speedup vs baseline: 2.2844x; 2.2844x over previous
#include <cuda_runtime.h>
#include <cuda_bf16.h>
#include <cstdint>

#define BB 16
#define CC 64
#define NN 2048
#define TQ 64      // queries per CTA
#define TM 128     // candidates per tile
#define RS 144     // bf16 tile row stride in BYTES (128 data + 16 pad)
#define SROW 129   // fp32 score-tile row stride (words)

// smem byte offsets
#define QHI 0                  // 64*144 = 9216
#define QLO 9216
#define MB0 18432              // M buffer 0: hi @ +0, lo @ +18432 (each 128*144)
#define MB1 55296              // M buffer 1
#define XX0 92160              // 128 fp32 norms, buffer 0
#define XX1 92672
#define SM_TOTAL 93184

// ---------------- scratch (no allocation allowed) ----------------
__device__ __nv_bfloat16 g_hi[BB * NN * CC];   // [b][n][c], 128B rows
__device__ __nv_bfloat16 g_lo[BB * NN * CC];
__device__ float         g_xx[BB * NN];
__device__ int           g_idx[BB * NN * 8];

__device__ __forceinline__ uint32_t smem_u32(const void* p) {
    uint32_t a;
    asm("{ .reg .u64 t; cvta.to.shared.u64 t, %1; cvt.u32.u64 %0, t; }" : "=r"(a) : "l"(p));
    return a;
}
__device__ __forceinline__ void ldsm4(uint32_t& r0, uint32_t& r1, uint32_t& r2, uint32_t& r3,
                                      uint32_t addr) {
    asm volatile("ldmatrix.sync.aligned.m8n8.x4.shared.b16 {%0,%1,%2,%3}, [%4];"
                 : "=r"(r0), "=r"(r1), "=r"(r2), "=r"(r3) : "r"(addr));
}
__device__ __forceinline__ void mma16816(float* c, const uint32_t* a, uint32_t b0, uint32_t b1) {
    asm volatile(
        "mma.sync.aligned.m16n8k16.row.col.f32.bf16.bf16.f32 "
        "{%0,%1,%2,%3}, {%4,%5,%6,%7}, {%8,%9}, {%0,%1,%2,%3};"
        : "+f"(c[0]), "+f"(c[1]), "+f"(c[2]), "+f"(c[3])
        : "r"(a[0]), "r"(a[1]), "r"(a[2]), "r"(a[3]), "r"(b0), "r"(b1));
}
__device__ __forceinline__ void cp16(uint32_t dst, const void* src) {
    asm volatile("cp.async.cg.shared.global [%0], [%1], 16;" :: "r"(dst), "l"(src));
}
#define CP_COMMIT() asm volatile("cp.async.commit_group;" ::: "memory")
#define CP_WAIT0()  asm volatile("cp.async.wait_group 0;" ::: "memory")

// ---------------------------------------------------------------------------
// Prep: hi/lo bf16 split in transposed [b][n][c] layout + fp32 norms.
// ---------------------------------------------------------------------------
__global__ void prep_kernel(const float* __restrict__ x) {
    int b = blockIdx.y;
    int n = blockIdx.x * 128 + threadIdx.x;
    const float* xp = x + b * CC * NN + n;
    __nv_bfloat162 hi2[32], lo2[32];
    float s = 0.f;
#pragma unroll
    for (int c2 = 0; c2 < 32; ++c2) {
        float v0 = xp[(2 * c2) * NN];
        float v1 = xp[(2 * c2 + 1) * NN];
        s = fmaf(v0, v0, s);
        s = fmaf(v1, v1, s);
        __nv_bfloat16 h0 = __float2bfloat16(v0);
        __nv_bfloat16 h1 = __float2bfloat16(v1);
        float r0 = v0 - __bfloat162float(h0);
        float r1 = v1 - __bfloat162float(h1);
        hi2[c2] = __halves2bfloat162(h0, h1);
        lo2[c2] = __halves2bfloat162(__float2bfloat16(r0), __float2bfloat16(r1));
    }
    g_xx[b * NN + n] = s;
    size_t rowo = (size_t)(b * NN + n) * CC;
    uint4* dh = (uint4*)(g_hi + rowo);
    uint4* dl = (uint4*)(g_lo + rowo);
    const uint4* sh = (const uint4*)hi2;
    const uint4* sl = (const uint4*)lo2;
#pragma unroll
    for (int i = 0; i < 8; ++i) { dh[i] = sh[i]; dl[i] = sl[i]; }
}

// ---------------------------------------------------------------------------
// Prefetch one M tile (hi+lo, 128 rows) + its 128 norms into buffer `buf`.
// 8 cp.async per thread + commit.
// ---------------------------------------------------------------------------
__device__ __forceinline__ void prefetch_tile(uint32_t sb, const char* sm, int buf,
                                              int b, int mb, int tid) {
    const uint4* mh = (const uint4*)(g_hi + (size_t)(b * NN + mb) * CC);
    const uint4* ml = (const uint4*)(g_lo + (size_t)(b * NN + mb) * CC);
    const uint32_t base = sb + (buf ? MB1 : MB0);
#pragma unroll
    for (int k = 0; k < 8; ++k) {
        int i = tid + k * 256;               // 0..2047
        int half = i >> 10;                  // 0 = hi, 1 = lo
        int r    = (i >> 3) & 127;
        int seg  = i & 7;
        const uint4* src = (half ? ml : mh) + r * 8 + seg;
        cp16(base + half * 18432 + r * RS + seg * 16, src);
    }
    if (tid < 32)
        cp16(sb + (buf ? XX1 : XX0) + tid * 16, g_xx + b * NN + mb + tid * 4);
    CP_COMMIT();
    (void)sm;
}

// ---------------------------------------------------------------------------
// KNN: R4 structure (64 queries x 16 M-tiles, persistent 4-way scan lists)
// + cp.async double-buffered M tiles.
// ---------------------------------------------------------------------------
__global__ void __launch_bounds__(256, 2) knn_kernel() {
    extern __shared__ char sm[];
    const uint32_t sb = smem_u32(sm);
    const int tid  = threadIdx.x;
    const int lane = tid & 31;
    const int w    = tid >> 5;
    const int wm   = (w & 1) * 32;        // warp query offset (0/32)
    const int wn   = (w >> 1) * 32;       // warp candidate offset (0..96)
    const int b    = blockIdx.y;
    const int qbase = blockIdx.x * TQ;

    // Load Q tiles (regular stores; covered by first barrier)
    {
        const uint4* qh = (const uint4*)(g_hi + (size_t)(b * NN + qbase) * CC);
        const uint4* ql = (const uint4*)(g_lo + (size_t)(b * NN + qbase) * CC);
        for (int i = tid; i < TQ * 8; i += 256) {
            int row = i >> 3, seg = i & 7;
            int o = row * RS + seg * 16;
            *(uint4*)(sm + QHI + o) = qh[i];
            *(uint4*)(sm + QLO + o) = ql[i];
        }
    }
    // Prefetch M tile 0 into buffer 0
    prefetch_tile(sb, sm, 0, b, 0, tid);

    float val9[9];
    int   idx9[9];
#pragma unroll
    for (int k = 0; k < 9; ++k) { val9[k] = -3.4e38f; idx9[k] = -1; }

    const int qown = tid & 63;     // query this thread scans
    const int qtr  = tid >> 6;     // candidate quarter (32 wide)

    const int lrow = lane & 15;
    const int lcol = (lane >> 4) * 16;
    const uint32_t aHiB = sb + QHI + (wm + lrow) * RS + lcol;
    const uint32_t aLoB = sb + QLO + (wm + lrow) * RS + lcol;

    for (int mt = 0; mt < 16; ++mt) {
        const int cur = mt & 1;
        const uint32_t mbase = sb + (cur ? MB1 : MB0);

        CP_WAIT0();
        __syncthreads();   // cur buffer ready; previous scan done (S region free)

        if (mt < 15) prefetch_tile(sb, sm, cur ^ 1, b, (mt + 1) * TM, tid);

        // ---- MMA: 64x128 tile, 3-pass bf16 split ----
        float acc[2][4][4];
#pragma unroll
        for (int i = 0; i < 2; ++i)
#pragma unroll
            for (int j = 0; j < 4; ++j)
#pragma unroll
                for (int k = 0; k < 4; ++k) acc[i][j][k] = 0.f;

        const uint32_t bHiB = mbase + (wn + lrow) * RS + lcol;
        const uint32_t bLoB = mbase + 18432 + (wn + lrow) * RS + lcol;

#pragma unroll
        for (int ks = 0; ks < 4; ++ks) {
            const int ko = ks * 32;
            uint32_t aH[2][4], aL[2][4], bH[4][2], bL[4][2];
#pragma unroll
            for (int m2 = 0; m2 < 2; ++m2) {
                ldsm4(aH[m2][0], aH[m2][1], aH[m2][2], aH[m2][3], aHiB + m2 * 16 * RS + ko);
                ldsm4(aL[m2][0], aL[m2][1], aL[m2][2], aL[m2][3], aLoB + m2 * 16 * RS + ko);
            }
#pragma unroll
            for (int np = 0; np < 2; ++np) {
                uint32_t r0, r1, r2, r3;
                ldsm4(r0, r1, r2, r3, bHiB + np * 16 * RS + ko);
                bH[np * 2][0] = r0; bH[np * 2][1] = r2;
                bH[np * 2 + 1][0] = r1; bH[np * 2 + 1][1] = r3;
                ldsm4(r0, r1, r2, r3, bLoB + np * 16 * RS + ko);
                bL[np * 2][0] = r0; bL[np * 2][1] = r2;
                bL[np * 2 + 1][0] = r1; bL[np * 2 + 1][1] = r3;
            }
#pragma unroll
            for (int m2 = 0; m2 < 2; ++m2)
#pragma unroll
                for (int j = 0; j < 4; ++j) {
                    mma16816(acc[m2][j], aH[m2], bH[j][0], bH[j][1]);
                    mma16816(acc[m2][j], aH[m2], bL[j][0], bL[j][1]);
                    mma16816(acc[m2][j], aL[m2], bH[j][0], bH[j][1]);
                }
        }
        __syncthreads();   // all MMA reads of cur done; S may overwrite cur

        // ---- spill S[q][m] into cur buffer region ----
        float* S = (float*)(sm + (cur ? MB1 : MB0));
        {
            const int r  = lane >> 2;
            const int cp = (lane & 3) * 2;
#pragma unroll
            for (int m2 = 0; m2 < 2; ++m2)
#pragma unroll
                for (int j = 0; j < 4; ++j) {
                    int row = wm + m2 * 16 + r;
                    int col = wn + j * 8 + cp;
                    S[row * SROW + col]           = acc[m2][j][0];
                    S[row * SROW + col + 1]       = acc[m2][j][1];
                    S[(row + 8) * SROW + col]     = acc[m2][j][2];
                    S[(row + 8) * SROW + col + 1] = acc[m2][j][3];
                }
        }
        __syncthreads();

        // ---- scan: 4 threads per query, 32 candidates each, persistent top-9 ----
        {
            const float* srow = &S[qown * SROW + qtr * 32];
            const float* xxp  = (const float*)(sm + (cur ? XX1 : XX0)) + qtr * 32;
            const int mofs = mt * TM + qtr * 32;
#pragma unroll 4
            for (int m = 0; m < 32; ++m) {
                float v = fmaf(2.f, srow[m], -xxp[m]);
                if (v > val9[8]) {
                    val9[8] = v;
                    idx9[8] = mofs + m;
#pragma unroll
                    for (int k = 8; k > 0; --k) {
                        if (val9[k] > val9[k - 1]) {
                            float tv = val9[k]; val9[k] = val9[k - 1]; val9[k - 1] = tv;
                            int   ti = idx9[k]; idx9[k] = idx9[k - 1]; idx9[k - 1] = ti;
                        }
                    }
                }
            }
        }
    }

    // Stable 4-way merge per query (val desc, idx asc — matches top_k)
    __syncthreads();
    float* MV = (float*)(sm + MB0);                      // [4*64][9]
    int*   MI = (int*)(sm + MB0 + 4 * 64 * 9 * 4);       // [4*64][9]
#pragma unroll
    for (int k = 0; k < 9; ++k) {
        MV[(qtr * 64 + qown) * 9 + k] = val9[k];
        MI[(qtr * 64 + qown) * 9 + k] = idx9[k];
    }
    __syncthreads();
    if (tid < TQ) {
        int p[4] = {0, 0, 0, 0};
        int* gout = &g_idx[(size_t)(b * NN + qbase + tid) * 8];
#pragma unroll
        for (int k = 0; k < 9; ++k) {
            float bv = -3.4e38f;
            int   bi = 0x7FFFFFFF, bl = 0;
#pragma unroll
            for (int l = 0; l < 4; ++l) {
                if (p[l] < 9) {
                    float v = MV[(l * 64 + tid) * 9 + p[l]];
                    int   i = MI[(l * 64 + tid) * 9 + p[l]];
                    if (v > bv || (v == bv && i < bi)) { bv = v; bi = i; bl = l; }
                }
            }
            ++p[bl];
            if (k > 0) gout[k - 1] = bi;
        }
    }
}

// ---------------------------------------------------------------------------
// Output assembly:
// out[b,c,n] = x[b,c,n];  out[b,c,N+n] = mean_k x[b,c,idx[b,n,k]]
// ---------------------------------------------------------------------------
__global__ void gather_kernel(const float* __restrict__ x, float* __restrict__ out) {
    __shared__ float row[NN];
    int b = blockIdx.x >> 6;
    int c = blockIdx.x & 63;
    const float* xr = x + (b * CC + c) * NN;
    for (int n = threadIdx.x; n < NN; n += blockDim.x) row[n] = xr[n];
    __syncthreads();
    const int4* gi = (const int4*)(g_idx + (size_t)b * NN * 8);
    float* o = out + (size_t)(b * CC + c) * (2 * NN);
    for (int n = threadIdx.x; n < NN; n += blockDim.x) {
        o[n] = row[n];
        int4 i0 = gi[n * 2];
        int4 i1 = gi[n * 2 + 1];
        float s = row[i0.x] + row[i0.y] + row[i0.z] + row[i0.w]
                + row[i1.x] + row[i1.y] + row[i1.z] + row[i1.w];
        o[NN + n] = s * 0.125f;
    }
}

// ---------------------------------------------------------------------------
extern "C" void kernel_launch(void* const* d_in, const int* in_sizes, int n_in,
                              void* d_out, int out_size) {
    (void)in_sizes; (void)n_in; (void)out_size;
    const float* x = (const float*)d_in[0];
    float* out = (float*)d_out;

    prep_kernel<<<dim3(16, 16), 128>>>(x);

    cudaFuncSetAttribute(knn_kernel, cudaFuncAttributeMaxDynamicSharedMemorySize, SM_TOTAL);
    knn_kernel<<<dim3(NN / TQ, BB), 256, SM_TOTAL>>>();

    gather_kernel<<<BB * CC, 256>>>(x, out);
}